// round 1
// baseline (speedup 1.0000x reference)
#include <cuda_runtime.h>
#include <math_constants.h>
#include <cstddef>

// ---------------------------------------------------------------------------
// INLAttentionBlock: GroupNorm -> 1x1 qkv -> MHA (flash) -> 3x INL Euler
//                    -> 1x1 proj -> residual.
// B=8, C=512, S=H*W=1024, heads=8, hd=64, groups=8.
// All fp32 SIMT baseline (correctness first; tensor-core rounds follow).
// ---------------------------------------------------------------------------

#define BATCH 8
#define CH    512
#define SEQ   1024
#define NHEAD 8
#define HDIM  64
#define NGRP  8
#define DT_STEP 0.1f
#define EPS_GN  1e-5f

// Scratch (static device globals; no allocation allowed).
__device__ __align__(128) float g_hn [(size_t)BATCH * SEQ * CH];        // [B,S,C]
__device__ __align__(128) float g_qkv[(size_t)BATCH * 3 * CH * SEQ];    // [B,3C,S]
__device__ __align__(128) float g_hfA[(size_t)BATCH * SEQ * CH];        // [B,S,C]
__device__ __align__(128) float g_hfB[(size_t)BATCH * SEQ * CH];        // [B,S,C]

// ---------------------------------------------------------------------------
// GroupNorm: one block per (batch, group). Computes mean/var, then writes the
// normalized result TRANSPOSED to [B,S,C] via a shared-memory 64x64 tile.
// ---------------------------------------------------------------------------
__global__ void __launch_bounds__(256) gn_kernel(
    const float* __restrict__ x, const float* __restrict__ scale,
    const float* __restrict__ bias, float* __restrict__ hn)
{
    __shared__ float tile[64][65];
    __shared__ float red[18];

    const int b = blockIdx.x >> 3;
    const int g = blockIdx.x & 7;
    const int tid = threadIdx.x;
    const float* xg = x + ((size_t)b * CH + g * 64) * SEQ;   // 64 ch x 1024 s

    float s = 0.f, ss = 0.f;
    for (int i = tid; i < 64 * SEQ; i += 256) {
        float v = xg[i];
        s += v; ss += v * v;
    }
    #pragma unroll
    for (int o = 16; o; o >>= 1) {
        s  += __shfl_down_sync(0xffffffffu, s,  o);
        ss += __shfl_down_sync(0xffffffffu, ss, o);
    }
    if ((tid & 31) == 0) { red[tid >> 5] = s; red[8 + (tid >> 5)] = ss; }
    __syncthreads();
    if (tid == 0) {
        float S = 0.f, SS = 0.f;
        #pragma unroll
        for (int w = 0; w < 8; w++) { S += red[w]; SS += red[8 + w]; }
        red[16] = S * (1.f / 65536.f);
        red[17] = SS * (1.f / 65536.f);
    }
    __syncthreads();
    const float mean = red[16];
    const float rstd = rsqrtf(red[17] - mean * mean + EPS_GN);

    float* hnb = hn + (size_t)b * SEQ * CH + g * 64;
    for (int s0 = 0; s0 < SEQ; s0 += 64) {
        __syncthreads();
        #pragma unroll
        for (int r = 0; r < 16; r++) {
            int idx = r * 256 + tid;
            int c = idx >> 6, si = idx & 63;
            tile[c][si] = xg[(size_t)c * SEQ + s0 + si];
        }
        __syncthreads();
        #pragma unroll
        for (int r = 0; r < 16; r++) {
            int idx = r * 256 + tid;
            int c = idx & 63, si = idx >> 6;
            int ch = g * 64 + c;
            hnb[(size_t)(s0 + si) * CH + c] =
                (tile[c][si] - mean) * rstd * scale[ch] + bias[ch];
        }
    }
}

// ---------------------------------------------------------------------------
// Generic NT GEMM: Out[m,n] = sum_k A[m,k] * Bm[n,k]  (+ fused epilogue)
//   MODE 0: qkv  : C = acc + bias[m]
//   MODE 1: INL  : C = extra[m,n] + DT * tanh(acc + bias[n])
//   MODE 2: proj : C = extra[m,n] + acc + bias[m]   (extra = residual x)
// Tiles 128x128x16, 256 threads, 8x8 per thread. All dims divide tiles.
// ---------------------------------------------------------------------------
template <int MODE>
__global__ void __launch_bounds__(256) gemm_nt(
    const float* __restrict__ A, const float* __restrict__ Bm,
    const float* __restrict__ bias, const float* __restrict__ extra,
    float* __restrict__ C, int M, int N, int K,
    size_t sB, size_t sC, size_t sE)
{
    __shared__ float As[16][132];
    __shared__ float Bs[16][132];

    const int tid = threadIdx.x;
    const int tx = tid & 15, ty = tid >> 4;
    const size_t bz = blockIdx.z;
    const float* gA = A + (size_t)blockIdx.y * 128 * K;
    const float* gB = Bm + bz * sB + (size_t)blockIdx.x * 128 * K;

    float acc[8][8];
    #pragma unroll
    for (int i = 0; i < 8; i++)
        #pragma unroll
        for (int j = 0; j < 8; j++) acc[i][j] = 0.f;

    for (int k0 = 0; k0 < K; k0 += 16) {
        #pragma unroll
        for (int u = 0; u < 2; u++) {
            int f = tid + u * 256;        // 512 float4 per matrix tile
            int row = f >> 2;
            int kk = (f & 3) << 2;
            float4 va = *(const float4*)(gA + (size_t)row * K + k0 + kk);
            As[kk + 0][row] = va.x; As[kk + 1][row] = va.y;
            As[kk + 2][row] = va.z; As[kk + 3][row] = va.w;
            float4 vb = *(const float4*)(gB + (size_t)row * K + k0 + kk);
            Bs[kk + 0][row] = vb.x; Bs[kk + 1][row] = vb.y;
            Bs[kk + 2][row] = vb.z; Bs[kk + 3][row] = vb.w;
        }
        __syncthreads();
        #pragma unroll
        for (int kk = 0; kk < 16; kk++) {
            float4 a0 = *(const float4*)&As[kk][ty * 8];
            float4 a1 = *(const float4*)&As[kk][ty * 8 + 4];
            float4 b0 = *(const float4*)&Bs[kk][tx * 8];
            float4 b1 = *(const float4*)&Bs[kk][tx * 8 + 4];
            float av[8] = {a0.x, a0.y, a0.z, a0.w, a1.x, a1.y, a1.z, a1.w};
            float bv[8] = {b0.x, b0.y, b0.z, b0.w, b1.x, b1.y, b1.z, b1.w};
            #pragma unroll
            for (int i = 0; i < 8; i++)
                #pragma unroll
                for (int j = 0; j < 8; j++)
                    acc[i][j] = fmaf(av[i], bv[j], acc[i][j]);
        }
        __syncthreads();
    }

    const int mbase = blockIdx.y * 128 + ty * 8;
    const int nbase = blockIdx.x * 128 + tx * 8;
    float* gC = C + bz * sC;

    #pragma unroll
    for (int i = 0; i < 8; i++) {
        const int m = mbase + i;
        float o[8];
        if (MODE == 0) {
            const float bv = bias[m];
            #pragma unroll
            for (int j = 0; j < 8; j++) o[j] = acc[i][j] + bv;
        } else if (MODE == 1) {
            #pragma unroll
            for (int j = 0; j < 8; j++) {
                float y = tanhf(acc[i][j] + bias[nbase + j]);
                o[j] = extra[(size_t)m * N + nbase + j] + DT_STEP * y;
            }
        } else {
            const float bv = bias[m];
            #pragma unroll
            for (int j = 0; j < 8; j++)
                o[j] = extra[bz * sE + (size_t)m * N + nbase + j] + acc[i][j] + bv;
        }
        *(float4*)(gC + (size_t)m * N + nbase) =
            make_float4(o[0], o[1], o[2], o[3]);
        *(float4*)(gC + (size_t)m * N + nbase + 4) =
            make_float4(o[4], o[5], o[6], o[7]);
    }
}

// ---------------------------------------------------------------------------
// Flash attention: one block per (q-tile of 64, b*8+head). hd=64, S=1024.
// Q,K stored [d][s] in qkv buffer (s contiguous). Online softmax.
// Output written directly in [B,S,C] layout for the INL stage.
// Shared: Qs/Ks/Vt/Ps each [64][68] fp32 -> 69632 B dynamic.
// ---------------------------------------------------------------------------
#define FLASH_SMEM (4 * 64 * 68 * 4)

__global__ void __launch_bounds__(256) flash_kernel(
    const float* __restrict__ qkv, float* __restrict__ out)
{
    extern __shared__ float sm[];
    float (*Qs)[68] = (float (*)[68])(sm);
    float (*Ks)[68] = (float (*)[68])(sm + 64 * 68);
    float (*Vt)[68] = (float (*)[68])(sm + 2 * 64 * 68);
    float (*Ps)[68] = (float (*)[68])(sm + 3 * 64 * 68);

    const int tid = threadIdx.x;
    const int tx = tid & 15, ty = tid >> 4;
    const int s0 = blockIdx.x * 64;
    const int b = blockIdx.y >> 3, n = blockIdx.y & 7;

    const float* qb = qkv + ((size_t)b * 3 * CH + n * HDIM) * SEQ;
    const float* kb = qb + (size_t)CH * SEQ;
    const float* vb = qb + (size_t)2 * CH * SEQ;

    // Load Q tile [64 d][64 qi], pre-scaled by 1/sqrt(hd).
    #pragma unroll
    for (int r = 0; r < 4; r++) {
        int f = r * 256 + tid;          // 1024 float4
        int d = f >> 4;
        int c4 = (f & 15) << 2;
        float4 v = *(const float4*)(qb + (size_t)d * SEQ + s0 + c4);
        v.x *= 0.125f; v.y *= 0.125f; v.z *= 0.125f; v.w *= 0.125f;
        *(float4*)&Qs[d][c4] = v;
    }

    float m[4], l[4], O[4][4];
    #pragma unroll
    for (int i = 0; i < 4; i++) {
        m[i] = -CUDART_INF_F; l[i] = 0.f;
        #pragma unroll
        for (int j = 0; j < 4; j++) O[i][j] = 0.f;
    }

    for (int t0 = 0; t0 < SEQ; t0 += 64) {
        // K tile [d][t] (coalesced float4)
        #pragma unroll
        for (int r = 0; r < 4; r++) {
            int f = r * 256 + tid;
            int d = f >> 4;
            int c4 = (f & 15) << 2;
            *(float4*)&Ks[d][c4] = *(const float4*)(kb + (size_t)d * SEQ + t0 + c4);
        }
        // V tile transposed to [t][d] (coalesced scalar reads over t)
        #pragma unroll
        for (int r = 0; r < 16; r++) {
            int f = r * 256 + tid;      // 4096 scalars
            int d = f >> 6;
            int t = f & 63;
            Vt[t][d] = vb[(size_t)d * SEQ + t0 + t];
        }
        __syncthreads();

        // Scores: s[i][j] for qi=ty*4+i, t=tx*4+j
        float s[4][4];
        #pragma unroll
        for (int i = 0; i < 4; i++)
            #pragma unroll
            for (int j = 0; j < 4; j++) s[i][j] = 0.f;

        #pragma unroll 8
        for (int d = 0; d < 64; d++) {
            float4 q4 = *(const float4*)&Qs[d][ty * 4];
            float4 k4 = *(const float4*)&Ks[d][tx * 4];
            float qa[4] = {q4.x, q4.y, q4.z, q4.w};
            float ka[4] = {k4.x, k4.y, k4.z, k4.w};
            #pragma unroll
            for (int i = 0; i < 4; i++)
                #pragma unroll
                for (int j = 0; j < 4; j++)
                    s[i][j] = fmaf(qa[i], ka[j], s[i][j]);
        }

        // Online softmax per qi row (reduce across the 16 tx lanes).
        #pragma unroll
        for (int i = 0; i < 4; i++) {
            float mx = fmaxf(fmaxf(s[i][0], s[i][1]), fmaxf(s[i][2], s[i][3]));
            #pragma unroll
            for (int o = 1; o < 16; o <<= 1)
                mx = fmaxf(mx, __shfl_xor_sync(0xffffffffu, mx, o));
            float mnew = fmaxf(m[i], mx);
            float corr = __expf(m[i] - mnew);
            m[i] = mnew;
            float p0 = __expf(s[i][0] - mnew);
            float p1 = __expf(s[i][1] - mnew);
            float p2 = __expf(s[i][2] - mnew);
            float p3 = __expf(s[i][3] - mnew);
            float ls = p0 + p1 + p2 + p3;
            #pragma unroll
            for (int o = 1; o < 16; o <<= 1)
                ls += __shfl_xor_sync(0xffffffffu, ls, o);
            l[i] = l[i] * corr + ls;
            #pragma unroll
            for (int j = 0; j < 4; j++) O[i][j] *= corr;
            *(float4*)&Ps[ty * 4 + i][tx * 4] = make_float4(p0, p1, p2, p3);
        }
        __syncwarp();   // Ps rows are warp-private (ty pairs per warp)

        // O[qi][d] += sum_t P[qi][t] * V[t][d]
        #pragma unroll 8
        for (int t = 0; t < 64; t++) {
            float4 v4 = *(const float4*)&Vt[t][tx * 4];
            float va[4] = {v4.x, v4.y, v4.z, v4.w};
            float pa[4];
            #pragma unroll
            for (int i = 0; i < 4; i++) pa[i] = Ps[ty * 4 + i][t];
            #pragma unroll
            for (int i = 0; i < 4; i++)
                #pragma unroll
                for (int j = 0; j < 4; j++)
                    O[i][j] = fmaf(pa[i], va[j], O[i][j]);
        }
        __syncthreads();
    }

    // Write O/l to hf layout [B,S,C], c = n*64 + d
    #pragma unroll
    for (int i = 0; i < 4; i++) {
        float inv = 1.f / l[i];
        size_t row = (size_t)b * SEQ + s0 + ty * 4 + i;
        *(float4*)&out[row * CH + n * HDIM + tx * 4] =
            make_float4(O[i][0] * inv, O[i][1] * inv, O[i][2] * inv, O[i][3] * inv);
    }
}

// ---------------------------------------------------------------------------
// Launch
// ---------------------------------------------------------------------------
extern "C" void kernel_launch(void* const* d_in, const int* in_sizes, int n_in,
                              void* d_out, int out_size)
{
    const float* x        = (const float*)d_in[0];
    const float* gn_scale = (const float*)d_in[1];
    const float* gn_bias  = (const float*)d_in[2];
    const float* qkv_w    = (const float*)d_in[3];
    const float* qkv_b    = (const float*)d_in[4];
    const float* proj_w   = (const float*)d_in[5];
    const float* proj_b   = (const float*)d_in[6];
    const float* inl_w    = (const float*)d_in[7];
    const float* inl_b    = (const float*)d_in[8];
    float* out = (float*)d_out;

    float *hn, *qkv, *hfA, *hfB;
    cudaGetSymbolAddress((void**)&hn,  g_hn);
    cudaGetSymbolAddress((void**)&qkv, g_qkv);
    cudaGetSymbolAddress((void**)&hfA, g_hfA);
    cudaGetSymbolAddress((void**)&hfB, g_hfB);

    // 1) GroupNorm -> g_hn [B,S,C]
    gn_kernel<<<BATCH * NGRP, 256>>>(x, gn_scale, gn_bias, hn);

    // 2) qkv = W_qkv @ hn^T per batch -> g_qkv [B,3C,S]
    gemm_nt<0><<<dim3(SEQ / 128, (3 * CH) / 128, BATCH), 256>>>(
        qkv_w, hn, qkv_b, nullptr, qkv,
        3 * CH, SEQ, CH,
        (size_t)SEQ * CH, (size_t)3 * CH * SEQ, 0);

    // 3) Flash attention -> g_hfA [B,S,C]
    cudaFuncSetAttribute(flash_kernel,
                         cudaFuncAttributeMaxDynamicSharedMemorySize, FLASH_SMEM);
    flash_kernel<<<dim3(SEQ / 64, BATCH * NHEAD), 256, FLASH_SMEM>>>(qkv, hfA);

    // 4) INL: 3x Euler steps, ping-pong A->B->A->B
    const dim3 inl_grid(CH / 128, (BATCH * SEQ) / 128, 1);
    gemm_nt<1><<<inl_grid, 256>>>(hfA, inl_w, inl_b, hfA, hfB,
                                  BATCH * SEQ, CH, CH, 0, 0, 0);
    gemm_nt<1><<<inl_grid, 256>>>(hfB, inl_w, inl_b, hfB, hfA,
                                  BATCH * SEQ, CH, CH, 0, 0, 0);
    gemm_nt<1><<<inl_grid, 256>>>(hfA, inl_w, inl_b, hfA, hfB,
                                  BATCH * SEQ, CH, CH, 0, 0, 0);

    // 5) proj + residual -> out [B,C,H,W]
    gemm_nt<2><<<dim3(SEQ / 128, CH / 128, BATCH), 256>>>(
        proj_w, hfB, proj_b, x, out,
        CH, SEQ, CH,
        (size_t)SEQ * CH, (size_t)CH * SEQ, (size_t)CH * SEQ);
}

// round 11
// speedup vs baseline: 1.6141x; 1.6141x over previous
#include <cuda_runtime.h>
#include <math_constants.h>
#include <cstddef>
#include <cstdint>

// ---------------------------------------------------------------------------
// INLAttentionBlock: GroupNorm -> 1x1 qkv -> MHA (flash) -> 3x INL Euler
//                    -> 1x1 proj -> residual.
// B=8, C=512, S=H*W=1024, heads=8, hd=64, groups=8.
// R11 (= R2 resubmit; nine infra-failed rounds): GEMMs on tf32 mma.sync.
// ---------------------------------------------------------------------------

#define BATCH 8
#define CH    512
#define SEQ   1024
#define NHEAD 8
#define HDIM  64
#define NGRP  8
#define DT_STEP 0.1f
#define EPS_GN  1e-5f

// Scratch (static device globals; no allocation allowed).
__device__ __align__(128) float g_hn [(size_t)BATCH * SEQ * CH];        // [B,S,C]
__device__ __align__(128) float g_qkv[(size_t)BATCH * 3 * CH * SEQ];    // [B,3C,S]
__device__ __align__(128) float g_hfA[(size_t)BATCH * SEQ * CH];        // [B,S,C]
__device__ __align__(128) float g_hfB[(size_t)BATCH * SEQ * CH];        // [B,S,C]

__device__ __forceinline__ float to_tf32(float x) {
    float r;
    asm("cvt.rna.tf32.f32 %0, %1;" : "=f"(r) : "f"(x));
    return r;
}

__device__ __forceinline__ void mma_tf32(
    float& c0, float& c1, float& c2, float& c3,
    float a0, float a1, float a2, float a3,
    float b0, float b1)
{
    asm volatile(
        "mma.sync.aligned.m16n8k8.row.col.f32.tf32.tf32.f32 "
        "{%0,%1,%2,%3}, {%4,%5,%6,%7}, {%8,%9}, {%0,%1,%2,%3};\n"
        : "+f"(c0), "+f"(c1), "+f"(c2), "+f"(c3)
        : "r"(__float_as_uint(a0)), "r"(__float_as_uint(a1)),
          "r"(__float_as_uint(a2)), "r"(__float_as_uint(a3)),
          "r"(__float_as_uint(b0)), "r"(__float_as_uint(b1)));
}

// ---------------------------------------------------------------------------
// GroupNorm: one block per (batch, group). Computes mean/var, then writes the
// normalized result TRANSPOSED to [B,S,C] via a shared-memory 64x64 tile.
// ---------------------------------------------------------------------------
__global__ void __launch_bounds__(256) gn_kernel(
    const float* __restrict__ x, const float* __restrict__ scale,
    const float* __restrict__ bias, float* __restrict__ hn)
{
    __shared__ float tile[64][65];
    __shared__ float red[18];

    const int b = blockIdx.x >> 3;
    const int g = blockIdx.x & 7;
    const int tid = threadIdx.x;
    const float* xg = x + ((size_t)b * CH + g * 64) * SEQ;   // 64 ch x 1024 s

    float s = 0.f, ss = 0.f;
    for (int i = tid; i < 64 * SEQ; i += 256) {
        float v = xg[i];
        s += v; ss += v * v;
    }
    #pragma unroll
    for (int o = 16; o; o >>= 1) {
        s  += __shfl_down_sync(0xffffffffu, s,  o);
        ss += __shfl_down_sync(0xffffffffu, ss, o);
    }
    if ((tid & 31) == 0) { red[tid >> 5] = s; red[8 + (tid >> 5)] = ss; }
    __syncthreads();
    if (tid == 0) {
        float S = 0.f, SS = 0.f;
        #pragma unroll
        for (int w = 0; w < 8; w++) { S += red[w]; SS += red[8 + w]; }
        red[16] = S * (1.f / 65536.f);
        red[17] = SS * (1.f / 65536.f);
    }
    __syncthreads();
    const float mean = red[16];
    const float rstd = rsqrtf(red[17] - mean * mean + EPS_GN);

    float* hnb = hn + (size_t)b * SEQ * CH + g * 64;
    for (int s0 = 0; s0 < SEQ; s0 += 64) {
        __syncthreads();
        #pragma unroll
        for (int r = 0; r < 16; r++) {
            int idx = r * 256 + tid;
            int c = idx >> 6, si = idx & 63;
            tile[c][si] = xg[(size_t)c * SEQ + s0 + si];
        }
        __syncthreads();
        #pragma unroll
        for (int r = 0; r < 16; r++) {
            int idx = r * 256 + tid;
            int c = idx & 63, si = idx >> 6;
            int ch = g * 64 + c;
            hnb[(size_t)(s0 + si) * CH + c] =
                (tile[c][si] - mean) * rstd * scale[ch] + bias[ch];
        }
    }
}

// ---------------------------------------------------------------------------
// TF32 tensor-core NT GEMM: Out[m,n] = sum_k A[m,k] * Bm[n,k] (+ epilogue)
//   MODE 0: qkv  : C = acc + bias[m]
//   MODE 1: INL  : C = extra[m,n] + DT * tanh(acc + bias[n])
//   MODE 2: proj : C = extra[m,n] + acc + bias[m]   (extra = residual x)
// Tile 128x128x32, 256 threads = 8 warps (2 M x 4 N), warp tile 64x32 via
// m16n8k8 tf32 mma (4x4 mma tiles). Inputs rounded to tf32 at smem store.
// Smem row stride 36 -> fragment LDS is bank-conflict-free.
// ---------------------------------------------------------------------------
template <int MODE>
__global__ void __launch_bounds__(256, 2) gemm_nt(
    const float* __restrict__ A, const float* __restrict__ Bm,
    const float* __restrict__ bias, const float* __restrict__ extra,
    float* __restrict__ C, int M, int N, int K,
    size_t sB, size_t sC, size_t sE)
{
    __shared__ float As[128][36];
    __shared__ float Bs[128][36];

    const int tid  = threadIdx.x;
    const int lane = tid & 31;
    const int wid  = tid >> 5;
    const int warpM = (wid & 1) * 64;   // 2 warp rows of 64
    const int warpN = (wid >> 1) * 32;  // 4 warp cols of 32
    const int gid = lane >> 2;          // 0..7
    const int tig = lane & 3;           // 0..3

    const size_t bz = blockIdx.z;
    const float* gA = A + (size_t)blockIdx.y * 128 * K;
    const float* gB = Bm + bz * sB + (size_t)blockIdx.x * 128 * K;

    float acc[4][4][4];
    #pragma unroll
    for (int mt = 0; mt < 4; mt++)
        #pragma unroll
        for (int nt = 0; nt < 4; nt++)
            #pragma unroll
            for (int r = 0; r < 4; r++) acc[mt][nt][r] = 0.f;

    float4 ra[4], rb[4];
    // prefetch k-tile 0
    #pragma unroll
    for (int u = 0; u < 4; u++) {
        int f = tid + u * 256;           // 1024 float4 per tile
        int row = f >> 3;                // 8 float4 per row (32 floats)
        int kk = (f & 7) << 2;
        ra[u] = *(const float4*)(gA + (size_t)row * K + kk);
        rb[u] = *(const float4*)(gB + (size_t)row * K + kk);
    }

    for (int k0 = 0; k0 < K; k0 += 32) {
        // store prefetched tile to smem, rounding to tf32
        #pragma unroll
        for (int u = 0; u < 4; u++) {
            int f = tid + u * 256;
            int row = f >> 3;
            int kk = (f & 7) << 2;
            As[row][kk + 0] = to_tf32(ra[u].x);
            As[row][kk + 1] = to_tf32(ra[u].y);
            As[row][kk + 2] = to_tf32(ra[u].z);
            As[row][kk + 3] = to_tf32(ra[u].w);
            Bs[row][kk + 0] = to_tf32(rb[u].x);
            Bs[row][kk + 1] = to_tf32(rb[u].y);
            Bs[row][kk + 2] = to_tf32(rb[u].z);
            Bs[row][kk + 3] = to_tf32(rb[u].w);
        }
        __syncthreads();

        // prefetch next k-tile while doing mma
        if (k0 + 32 < K) {
            #pragma unroll
            for (int u = 0; u < 4; u++) {
                int f = tid + u * 256;
                int row = f >> 3;
                int kk = (f & 7) << 2;
                ra[u] = *(const float4*)(gA + (size_t)row * K + k0 + 32 + kk);
                rb[u] = *(const float4*)(gB + (size_t)row * K + k0 + 32 + kk);
            }
        }

        #pragma unroll
        for (int ks = 0; ks < 4; ks++) {
            const int kb = ks * 8;
            float af[4][4], bf[4][2];
            #pragma unroll
            for (int mt = 0; mt < 4; mt++) {
                int r = warpM + mt * 16 + gid;
                af[mt][0] = As[r    ][kb + tig];
                af[mt][1] = As[r + 8][kb + tig];
                af[mt][2] = As[r    ][kb + tig + 4];
                af[mt][3] = As[r + 8][kb + tig + 4];
            }
            #pragma unroll
            for (int nt = 0; nt < 4; nt++) {
                int r = warpN + nt * 8 + gid;
                bf[nt][0] = Bs[r][kb + tig];
                bf[nt][1] = Bs[r][kb + tig + 4];
            }
            #pragma unroll
            for (int mt = 0; mt < 4; mt++)
                #pragma unroll
                for (int nt = 0; nt < 4; nt++)
                    mma_tf32(acc[mt][nt][0], acc[mt][nt][1],
                             acc[mt][nt][2], acc[mt][nt][3],
                             af[mt][0], af[mt][1], af[mt][2], af[mt][3],
                             bf[nt][0], bf[nt][1]);
        }
        __syncthreads();
    }

    // Epilogue. c0,c1 at (gid, tig*2 / +1); c2,c3 at (gid+8, same cols).
    float* gC = C + bz * sC;
    const int mblk = blockIdx.y * 128;
    const int nblk = blockIdx.x * 128;

    #pragma unroll
    for (int mt = 0; mt < 4; mt++) {
        #pragma unroll
        for (int half = 0; half < 2; half++) {
            const int m = mblk + warpM + mt * 16 + gid + half * 8;
            #pragma unroll
            for (int nt = 0; nt < 4; nt++) {
                const int n = nblk + warpN + nt * 8 + tig * 2;
                float v0 = acc[mt][nt][half * 2 + 0];
                float v1 = acc[mt][nt][half * 2 + 1];
                float o0, o1;
                if (MODE == 0) {
                    const float bv = bias[m];
                    o0 = v0 + bv; o1 = v1 + bv;
                } else if (MODE == 1) {
                    o0 = extra[(size_t)m * N + n]     + DT_STEP * tanhf(v0 + bias[n]);
                    o1 = extra[(size_t)m * N + n + 1] + DT_STEP * tanhf(v1 + bias[n + 1]);
                } else {
                    const float bv = bias[m];
                    o0 = extra[bz * sE + (size_t)m * N + n]     + v0 + bv;
                    o1 = extra[bz * sE + (size_t)m * N + n + 1] + v1 + bv;
                }
                *(float2*)(gC + (size_t)m * N + n) = make_float2(o0, o1);
            }
        }
    }
}

// ---------------------------------------------------------------------------
// Flash attention: one block per (q-tile of 64, b*8+head). hd=64, S=1024.
// Q,K stored [d][s] in qkv buffer (s contiguous). Online softmax.
// Output written directly in [B,S,C] layout for the INL stage.
// Shared: Qs/Ks/Vt/Ps each [64][68] fp32 -> 69632 B dynamic.
// ---------------------------------------------------------------------------
#define FLASH_SMEM (4 * 64 * 68 * 4)

__global__ void __launch_bounds__(256) flash_kernel(
    const float* __restrict__ qkv, float* __restrict__ out)
{
    extern __shared__ float sm[];
    float (*Qs)[68] = (float (*)[68])(sm);
    float (*Ks)[68] = (float (*)[68])(sm + 64 * 68);
    float (*Vt)[68] = (float (*)[68])(sm + 2 * 64 * 68);
    float (*Ps)[68] = (float (*)[68])(sm + 3 * 64 * 68);

    const int tid = threadIdx.x;
    const int tx = tid & 15, ty = tid >> 4;
    const int s0 = blockIdx.x * 64;
    const int b = blockIdx.y >> 3, n = blockIdx.y & 7;

    const float* qb = qkv + ((size_t)b * 3 * CH + n * HDIM) * SEQ;
    const float* kb = qb + (size_t)CH * SEQ;
    const float* vb = qb + (size_t)2 * CH * SEQ;

    // Load Q tile [64 d][64 qi], pre-scaled by 1/sqrt(hd).
    #pragma unroll
    for (int r = 0; r < 4; r++) {
        int f = r * 256 + tid;          // 1024 float4
        int d = f >> 4;
        int c4 = (f & 15) << 2;
        float4 v = *(const float4*)(qb + (size_t)d * SEQ + s0 + c4);
        v.x *= 0.125f; v.y *= 0.125f; v.z *= 0.125f; v.w *= 0.125f;
        *(float4*)&Qs[d][c4] = v;
    }

    float m[4], l[4], O[4][4];
    #pragma unroll
    for (int i = 0; i < 4; i++) {
        m[i] = -CUDART_INF_F; l[i] = 0.f;
        #pragma unroll
        for (int j = 0; j < 4; j++) O[i][j] = 0.f;
    }

    for (int t0 = 0; t0 < SEQ; t0 += 64) {
        // K tile [d][t] (coalesced float4)
        #pragma unroll
        for (int r = 0; r < 4; r++) {
            int f = r * 256 + tid;
            int d = f >> 4;
            int c4 = (f & 15) << 2;
            *(float4*)&Ks[d][c4] = *(const float4*)(kb + (size_t)d * SEQ + t0 + c4);
        }
        // V tile transposed to [t][d] (coalesced scalar reads over t)
        #pragma unroll
        for (int r = 0; r < 16; r++) {
            int f = r * 256 + tid;      // 4096 scalars
            int d = f >> 6;
            int t = f & 63;
            Vt[t][d] = vb[(size_t)d * SEQ + t0 + t];
        }
        __syncthreads();

        // Scores: s[i][j] for qi=ty*4+i, t=tx*4+j
        float s[4][4];
        #pragma unroll
        for (int i = 0; i < 4; i++)
            #pragma unroll
            for (int j = 0; j < 4; j++) s[i][j] = 0.f;

        #pragma unroll 8
        for (int d = 0; d < 64; d++) {
            float4 q4 = *(const float4*)&Qs[d][ty * 4];
            float4 k4 = *(const float4*)&Ks[d][tx * 4];
            float qa[4] = {q4.x, q4.y, q4.z, q4.w};
            float ka[4] = {k4.x, k4.y, k4.z, k4.w};
            #pragma unroll
            for (int i = 0; i < 4; i++)
                #pragma unroll
                for (int j = 0; j < 4; j++)
                    s[i][j] = fmaf(qa[i], ka[j], s[i][j]);
        }

        // Online softmax per qi row (reduce across the 16 tx lanes).
        #pragma unroll
        for (int i = 0; i < 4; i++) {
            float mx = fmaxf(fmaxf(s[i][0], s[i][1]), fmaxf(s[i][2], s[i][3]));
            #pragma unroll
            for (int o = 1; o < 16; o <<= 1)
                mx = fmaxf(mx, __shfl_xor_sync(0xffffffffu, mx, o));
            float mnew = fmaxf(m[i], mx);
            float corr = __expf(m[i] - mnew);
            m[i] = mnew;
            float p0 = __expf(s[i][0] - mnew);
            float p1 = __expf(s[i][1] - mnew);
            float p2 = __expf(s[i][2] - mnew);
            float p3 = __expf(s[i][3] - mnew);
            float ls = p0 + p1 + p2 + p3;
            #pragma unroll
            for (int o = 1; o < 16; o <<= 1)
                ls += __shfl_xor_sync(0xffffffffu, ls, o);
            l[i] = l[i] * corr + ls;
            #pragma unroll
            for (int j = 0; j < 4; j++) O[i][j] *= corr;
            *(float4*)&Ps[ty * 4 + i][tx * 4] = make_float4(p0, p1, p2, p3);
        }
        __syncwarp();   // Ps rows are warp-private (ty pairs per warp)

        // O[qi][d] += sum_t P[qi][t] * V[t][d]
        #pragma unroll 8
        for (int t = 0; t < 64; t++) {
            float4 v4 = *(const float4*)&Vt[t][tx * 4];
            float va[4] = {v4.x, v4.y, v4.z, v4.w};
            float pa[4];
            #pragma unroll
            for (int i = 0; i < 4; i++) pa[i] = Ps[ty * 4 + i][t];
            #pragma unroll
            for (int i = 0; i < 4; i++)
                #pragma unroll
                for (int j = 0; j < 4; j++)
                    O[i][j] = fmaf(pa[i], va[j], O[i][j]);
        }
        __syncthreads();
    }

    // Write O/l to hf layout [B,S,C], c = n*64 + d
    #pragma unroll
    for (int i = 0; i < 4; i++) {
        float inv = 1.f / l[i];
        size_t row = (size_t)b * SEQ + s0 + ty * 4 + i;
        *(float4*)&out[row * CH + n * HDIM + tx * 4] =
            make_float4(O[i][0] * inv, O[i][1] * inv, O[i][2] * inv, O[i][3] * inv);
    }
}

// ---------------------------------------------------------------------------
// Launch
// ---------------------------------------------------------------------------
extern "C" void kernel_launch(void* const* d_in, const int* in_sizes, int n_in,
                              void* d_out, int out_size)
{
    const float* x        = (const float*)d_in[0];
    const float* gn_scale = (const float*)d_in[1];
    const float* gn_bias  = (const float*)d_in[2];
    const float* qkv_w    = (const float*)d_in[3];
    const float* qkv_b    = (const float*)d_in[4];
    const float* proj_w   = (const float*)d_in[5];
    const float* proj_b   = (const float*)d_in[6];
    const float* inl_w    = (const float*)d_in[7];
    const float* inl_b    = (const float*)d_in[8];
    float* out = (float*)d_out;

    float *hn, *qkv, *hfA, *hfB;
    cudaGetSymbolAddress((void**)&hn,  g_hn);
    cudaGetSymbolAddress((void**)&qkv, g_qkv);
    cudaGetSymbolAddress((void**)&hfA, g_hfA);
    cudaGetSymbolAddress((void**)&hfB, g_hfB);

    // 1) GroupNorm -> g_hn [B,S,C]
    gn_kernel<<<BATCH * NGRP, 256>>>(x, gn_scale, gn_bias, hn);

    // 2) qkv = W_qkv @ hn^T per batch -> g_qkv [B,3C,S]
    gemm_nt<0><<<dim3(SEQ / 128, (3 * CH) / 128, BATCH), 256>>>(
        qkv_w, hn, qkv_b, nullptr, qkv,
        3 * CH, SEQ, CH,
        (size_t)SEQ * CH, (size_t)3 * CH * SEQ, 0);

    // 3) Flash attention -> g_hfA [B,S,C]
    cudaFuncSetAttribute(flash_kernel,
                         cudaFuncAttributeMaxDynamicSharedMemorySize, FLASH_SMEM);
    flash_kernel<<<dim3(SEQ / 64, BATCH * NHEAD), 256, FLASH_SMEM>>>(qkv, hfA);

    // 4) INL: 3x Euler steps, ping-pong A->B->A->B
    const dim3 inl_grid(CH / 128, (BATCH * SEQ) / 128, 1);
    gemm_nt<1><<<inl_grid, 256>>>(hfA, inl_w, inl_b, hfA, hfB,
                                  BATCH * SEQ, CH, CH, 0, 0, 0);
    gemm_nt<1><<<inl_grid, 256>>>(hfB, inl_w, inl_b, hfB, hfA,
                                  BATCH * SEQ, CH, CH, 0, 0, 0);
    gemm_nt<1><<<inl_grid, 256>>>(hfA, inl_w, inl_b, hfA, hfB,
                                  BATCH * SEQ, CH, CH, 0, 0, 0);

    // 5) proj + residual -> out [B,C,H,W]
    gemm_nt<2><<<dim3(SEQ / 128, CH / 128, BATCH), 256>>>(
        proj_w, hfB, proj_b, x, out,
        CH, SEQ, CH,
        (size_t)SEQ * CH, (size_t)CH * SEQ, (size_t)CH * SEQ);
}

// round 13
// speedup vs baseline: 2.4875x; 1.5410x over previous
#include <cuda_runtime.h>
#include <math_constants.h>
#include <cstddef>
#include <cstdint>

// ---------------------------------------------------------------------------
// INLAttentionBlock: GroupNorm -> 1x1 qkv -> MHA (flash) -> 3x INL Euler
//                    -> 1x1 proj -> residual.
// B=8, C=512, S=H*W=1024, heads=8, hd=64, groups=8.
// R13 (= R12 resubmit; device-busy infra failure): GEMMs + flash on tf32 mma.
// ---------------------------------------------------------------------------

#define BATCH 8
#define CH    512
#define SEQ   1024
#define NHEAD 8
#define HDIM  64
#define NGRP  8
#define DT_STEP 0.1f
#define EPS_GN  1e-5f

// Scratch (static device globals; no allocation allowed).
__device__ __align__(128) float g_hn [(size_t)BATCH * SEQ * CH];        // [B,S,C]
__device__ __align__(128) float g_qkv[(size_t)BATCH * 3 * CH * SEQ];    // [B,3C,S]
__device__ __align__(128) float g_hfA[(size_t)BATCH * SEQ * CH];        // [B,S,C]
__device__ __align__(128) float g_hfB[(size_t)BATCH * SEQ * CH];        // [B,S,C]

__device__ __forceinline__ float to_tf32(float x) {
    float r;
    asm("cvt.rna.tf32.f32 %0, %1;" : "=f"(r) : "f"(x));
    return r;
}

__device__ __forceinline__ void mma_tf32(
    float& c0, float& c1, float& c2, float& c3,
    float a0, float a1, float a2, float a3,
    float b0, float b1)
{
    asm volatile(
        "mma.sync.aligned.m16n8k8.row.col.f32.tf32.tf32.f32 "
        "{%0,%1,%2,%3}, {%4,%5,%6,%7}, {%8,%9}, {%0,%1,%2,%3};\n"
        : "+f"(c0), "+f"(c1), "+f"(c2), "+f"(c3)
        : "r"(__float_as_uint(a0)), "r"(__float_as_uint(a1)),
          "r"(__float_as_uint(a2)), "r"(__float_as_uint(a3)),
          "r"(__float_as_uint(b0)), "r"(__float_as_uint(b1)));
}

// ---------------------------------------------------------------------------
// GroupNorm: one block per (batch, group). Computes mean/var, then writes the
// normalized result TRANSPOSED to [B,S,C] via a shared-memory 64x64 tile.
// ---------------------------------------------------------------------------
__global__ void __launch_bounds__(256) gn_kernel(
    const float* __restrict__ x, const float* __restrict__ scale,
    const float* __restrict__ bias, float* __restrict__ hn)
{
    __shared__ float tile[64][65];
    __shared__ float red[18];

    const int b = blockIdx.x >> 3;
    const int g = blockIdx.x & 7;
    const int tid = threadIdx.x;
    const float* xg = x + ((size_t)b * CH + g * 64) * SEQ;   // 64 ch x 1024 s

    float s = 0.f, ss = 0.f;
    for (int i = tid; i < 64 * SEQ; i += 256) {
        float v = xg[i];
        s += v; ss += v * v;
    }
    #pragma unroll
    for (int o = 16; o; o >>= 1) {
        s  += __shfl_down_sync(0xffffffffu, s,  o);
        ss += __shfl_down_sync(0xffffffffu, ss, o);
    }
    if ((tid & 31) == 0) { red[tid >> 5] = s; red[8 + (tid >> 5)] = ss; }
    __syncthreads();
    if (tid == 0) {
        float S = 0.f, SS = 0.f;
        #pragma unroll
        for (int w = 0; w < 8; w++) { S += red[w]; SS += red[8 + w]; }
        red[16] = S * (1.f / 65536.f);
        red[17] = SS * (1.f / 65536.f);
    }
    __syncthreads();
    const float mean = red[16];
    const float rstd = rsqrtf(red[17] - mean * mean + EPS_GN);

    float* hnb = hn + (size_t)b * SEQ * CH + g * 64;
    for (int s0 = 0; s0 < SEQ; s0 += 64) {
        __syncthreads();
        #pragma unroll
        for (int r = 0; r < 16; r++) {
            int idx = r * 256 + tid;
            int c = idx >> 6, si = idx & 63;
            tile[c][si] = xg[(size_t)c * SEQ + s0 + si];
        }
        __syncthreads();
        #pragma unroll
        for (int r = 0; r < 16; r++) {
            int idx = r * 256 + tid;
            int c = idx & 63, si = idx >> 6;
            int ch = g * 64 + c;
            hnb[(size_t)(s0 + si) * CH + c] =
                (tile[c][si] - mean) * rstd * scale[ch] + bias[ch];
        }
    }
}

// ---------------------------------------------------------------------------
// TF32 tensor-core NT GEMM: Out[m,n] = sum_k A[m,k] * Bm[n,k] (+ epilogue)
//   MODE 0: qkv  : C = acc + bias[m]
//   MODE 1: INL  : C = extra[m,n] + DT * tanh(acc + bias[n])
//   MODE 2: proj : C = extra[m,n] + acc + bias[m]   (extra = residual x)
// Tile 128x128x32, 256 threads = 8 warps (2 M x 4 N), warp tile 64x32 via
// m16n8k8 tf32 mma (4x4 mma tiles). Inputs rounded to tf32 at smem store.
// Smem row stride 36 -> fragment LDS is bank-conflict-free.
// ---------------------------------------------------------------------------
template <int MODE>
__global__ void __launch_bounds__(256, 2) gemm_nt(
    const float* __restrict__ A, const float* __restrict__ Bm,
    const float* __restrict__ bias, const float* __restrict__ extra,
    float* __restrict__ C, int M, int N, int K,
    size_t sB, size_t sC, size_t sE)
{
    __shared__ float As[128][36];
    __shared__ float Bs[128][36];

    const int tid  = threadIdx.x;
    const int lane = tid & 31;
    const int wid  = tid >> 5;
    const int warpM = (wid & 1) * 64;   // 2 warp rows of 64
    const int warpN = (wid >> 1) * 32;  // 4 warp cols of 32
    const int gid = lane >> 2;          // 0..7
    const int tig = lane & 3;           // 0..3

    const size_t bz = blockIdx.z;
    const float* gA = A + (size_t)blockIdx.y * 128 * K;
    const float* gB = Bm + bz * sB + (size_t)blockIdx.x * 128 * K;

    float acc[4][4][4];
    #pragma unroll
    for (int mt = 0; mt < 4; mt++)
        #pragma unroll
        for (int nt = 0; nt < 4; nt++)
            #pragma unroll
            for (int r = 0; r < 4; r++) acc[mt][nt][r] = 0.f;

    float4 ra[4], rb[4];
    // prefetch k-tile 0
    #pragma unroll
    for (int u = 0; u < 4; u++) {
        int f = tid + u * 256;           // 1024 float4 per tile
        int row = f >> 3;                // 8 float4 per row (32 floats)
        int kk = (f & 7) << 2;
        ra[u] = *(const float4*)(gA + (size_t)row * K + kk);
        rb[u] = *(const float4*)(gB + (size_t)row * K + kk);
    }

    for (int k0 = 0; k0 < K; k0 += 32) {
        // store prefetched tile to smem, rounding to tf32
        #pragma unroll
        for (int u = 0; u < 4; u++) {
            int f = tid + u * 256;
            int row = f >> 3;
            int kk = (f & 7) << 2;
            As[row][kk + 0] = to_tf32(ra[u].x);
            As[row][kk + 1] = to_tf32(ra[u].y);
            As[row][kk + 2] = to_tf32(ra[u].z);
            As[row][kk + 3] = to_tf32(ra[u].w);
            Bs[row][kk + 0] = to_tf32(rb[u].x);
            Bs[row][kk + 1] = to_tf32(rb[u].y);
            Bs[row][kk + 2] = to_tf32(rb[u].z);
            Bs[row][kk + 3] = to_tf32(rb[u].w);
        }
        __syncthreads();

        // prefetch next k-tile while doing mma
        if (k0 + 32 < K) {
            #pragma unroll
            for (int u = 0; u < 4; u++) {
                int f = tid + u * 256;
                int row = f >> 3;
                int kk = (f & 7) << 2;
                ra[u] = *(const float4*)(gA + (size_t)row * K + k0 + 32 + kk);
                rb[u] = *(const float4*)(gB + (size_t)row * K + k0 + 32 + kk);
            }
        }

        #pragma unroll
        for (int ks = 0; ks < 4; ks++) {
            const int kb = ks * 8;
            float af[4][4], bf[4][2];
            #pragma unroll
            for (int mt = 0; mt < 4; mt++) {
                int r = warpM + mt * 16 + gid;
                af[mt][0] = As[r    ][kb + tig];
                af[mt][1] = As[r + 8][kb + tig];
                af[mt][2] = As[r    ][kb + tig + 4];
                af[mt][3] = As[r + 8][kb + tig + 4];
            }
            #pragma unroll
            for (int nt = 0; nt < 4; nt++) {
                int r = warpN + nt * 8 + gid;
                bf[nt][0] = Bs[r][kb + tig];
                bf[nt][1] = Bs[r][kb + tig + 4];
            }
            #pragma unroll
            for (int mt = 0; mt < 4; mt++)
                #pragma unroll
                for (int nt = 0; nt < 4; nt++)
                    mma_tf32(acc[mt][nt][0], acc[mt][nt][1],
                             acc[mt][nt][2], acc[mt][nt][3],
                             af[mt][0], af[mt][1], af[mt][2], af[mt][3],
                             bf[nt][0], bf[nt][1]);
        }
        __syncthreads();
    }

    // Epilogue. c0,c1 at (gid, tig*2 / +1); c2,c3 at (gid+8, same cols).
    float* gC = C + bz * sC;
    const int mblk = blockIdx.y * 128;
    const int nblk = blockIdx.x * 128;

    #pragma unroll
    for (int mt = 0; mt < 4; mt++) {
        #pragma unroll
        for (int half = 0; half < 2; half++) {
            const int m = mblk + warpM + mt * 16 + gid + half * 8;
            #pragma unroll
            for (int nt = 0; nt < 4; nt++) {
                const int n = nblk + warpN + nt * 8 + tig * 2;
                float v0 = acc[mt][nt][half * 2 + 0];
                float v1 = acc[mt][nt][half * 2 + 1];
                float o0, o1;
                if (MODE == 0) {
                    const float bv = bias[m];
                    o0 = v0 + bv; o1 = v1 + bv;
                } else if (MODE == 1) {
                    o0 = extra[(size_t)m * N + n]     + DT_STEP * tanhf(v0 + bias[n]);
                    o1 = extra[(size_t)m * N + n + 1] + DT_STEP * tanhf(v1 + bias[n + 1]);
                } else {
                    const float bv = bias[m];
                    o0 = extra[bz * sE + (size_t)m * N + n]     + v0 + bv;
                    o1 = extra[bz * sE + (size_t)m * N + n + 1] + v1 + bv;
                }
                *(float2*)(gC + (size_t)m * N + n) = make_float2(o0, o1);
            }
        }
    }
}

// ---------------------------------------------------------------------------
// Flash attention v2 (tf32 mma): one block per (q-tile of 64, b*8+head).
// 128 threads = 4 warps; each warp owns 16 query rows (one m16 tile) and
// sweeps all 64 keys per kv-tile (8 n8 tiles), hd=64 -> 8 k8 steps.
// Smem: Qs[q][d] (reused as Ps[q][t] after fragment preload), Ks[t][d]
// (transposed at load), Vs[d][t] (natural layout). All tf32-rounded.
// fp32 online softmax in C-fragments; row reduce = 2 quad shuffles.
// Smem 3*64*68*4 = 52224 B.
// ---------------------------------------------------------------------------
#define FLASH_SMEM (3 * 64 * 68 * 4)

__global__ void __launch_bounds__(128) flash_kernel(
    const float* __restrict__ qkv, float* __restrict__ out)
{
    extern __shared__ float sm[];
    float (*Qs)[68] = (float (*)[68])(sm);             // [q][d]; becomes Ps[q][t]
    float (*Ks)[68] = (float (*)[68])(sm + 64 * 68);   // [t][d]
    float (*Vs)[68] = (float (*)[68])(sm + 2 * 64 * 68); // [d][t]
    float (*Ps)[68] = Qs;

    const int tid  = threadIdx.x;
    const int lane = tid & 31;
    const int wid  = tid >> 5;       // 0..3
    const int gid  = lane >> 2;      // 0..7
    const int tig  = lane & 3;       // 0..3
    const int qw   = wid * 16;       // warp's q base within tile
    const int s0   = blockIdx.x * 64;
    const int b = blockIdx.y >> 3, n = blockIdx.y & 7;

    const float* qb = qkv + ((size_t)b * 3 * CH + n * HDIM) * SEQ;
    const float* kb = qb + (size_t)CH * SEQ;
    const float* vb = qb + (size_t)2 * CH * SEQ;

    // Load Q tile transposed -> Qs[q][d], tf32, pre-scaled by 1/sqrt(hd).
    #pragma unroll
    for (int i = 0; i < 8; i++) {
        int f = i * 128 + tid;          // 1024 float4
        int d = f >> 4;
        int q4 = (f & 15) << 2;
        float4 v = *(const float4*)(qb + (size_t)d * SEQ + s0 + q4);
        Qs[q4 + 0][d] = to_tf32(v.x * 0.125f);
        Qs[q4 + 1][d] = to_tf32(v.y * 0.125f);
        Qs[q4 + 2][d] = to_tf32(v.z * 0.125f);
        Qs[q4 + 3][d] = to_tf32(v.w * 0.125f);
    }
    __syncthreads();

    // Preload Q A-fragments (Qs region is reused as Ps afterwards).
    float qf[8][4];
    #pragma unroll
    for (int ks = 0; ks < 8; ks++) {
        qf[ks][0] = Qs[qw + gid    ][ks * 8 + tig];
        qf[ks][1] = Qs[qw + gid + 8][ks * 8 + tig];
        qf[ks][2] = Qs[qw + gid    ][ks * 8 + tig + 4];
        qf[ks][3] = Qs[qw + gid + 8][ks * 8 + tig + 4];
    }

    float m0 = -CUDART_INF_F, m1 = -CUDART_INF_F, l0 = 0.f, l1 = 0.f;
    float O[8][4];
    #pragma unroll
    for (int nt = 0; nt < 8; nt++)
        #pragma unroll
        for (int r = 0; r < 4; r++) O[nt][r] = 0.f;

    for (int t0 = 0; t0 < SEQ; t0 += 64) {
        __syncthreads();   // prev iteration's PV reads + Q-frag preload done

        // K tile transposed -> Ks[t][d]; V tile natural -> Vs[d][t]; tf32.
        #pragma unroll
        for (int i = 0; i < 8; i++) {
            int f = i * 128 + tid;
            int d = f >> 4;
            int t4 = (f & 15) << 2;
            float4 kv = *(const float4*)(kb + (size_t)d * SEQ + t0 + t4);
            Ks[t4 + 0][d] = to_tf32(kv.x);
            Ks[t4 + 1][d] = to_tf32(kv.y);
            Ks[t4 + 2][d] = to_tf32(kv.z);
            Ks[t4 + 3][d] = to_tf32(kv.w);
            float4 vv = *(const float4*)(vb + (size_t)d * SEQ + t0 + t4);
            Vs[d][t4 + 0] = to_tf32(vv.x);
            Vs[d][t4 + 1] = to_tf32(vv.y);
            Vs[d][t4 + 2] = to_tf32(vv.z);
            Vs[d][t4 + 3] = to_tf32(vv.w);
        }
        __syncthreads();

        // S[16 q][64 t] = Q K^T on tensor pipe.
        float c[8][4];
        #pragma unroll
        for (int nt = 0; nt < 8; nt++)
            #pragma unroll
            for (int r = 0; r < 4; r++) c[nt][r] = 0.f;

        #pragma unroll
        for (int ks = 0; ks < 8; ks++) {
            #pragma unroll
            for (int nt = 0; nt < 8; nt++) {
                float b0 = Ks[nt * 8 + gid][ks * 8 + tig];
                float b1 = Ks[nt * 8 + gid][ks * 8 + tig + 4];
                mma_tf32(c[nt][0], c[nt][1], c[nt][2], c[nt][3],
                         qf[ks][0], qf[ks][1], qf[ks][2], qf[ks][3],
                         b0, b1);
            }
        }

        // Online softmax. Rows gid (c0,c1) and gid+8 (c2,c3); each row is
        // spread over the 4 lanes of a quad -> shfl_xor 1,2 reduces it.
        float mx0 = -CUDART_INF_F, mx1 = -CUDART_INF_F;
        #pragma unroll
        for (int nt = 0; nt < 8; nt++) {
            mx0 = fmaxf(mx0, fmaxf(c[nt][0], c[nt][1]));
            mx1 = fmaxf(mx1, fmaxf(c[nt][2], c[nt][3]));
        }
        mx0 = fmaxf(mx0, __shfl_xor_sync(0xffffffffu, mx0, 1));
        mx0 = fmaxf(mx0, __shfl_xor_sync(0xffffffffu, mx0, 2));
        mx1 = fmaxf(mx1, __shfl_xor_sync(0xffffffffu, mx1, 1));
        mx1 = fmaxf(mx1, __shfl_xor_sync(0xffffffffu, mx1, 2));

        float mn0 = fmaxf(m0, mx0), mn1 = fmaxf(m1, mx1);
        float corr0 = __expf(m0 - mn0), corr1 = __expf(m1 - mn1);
        m0 = mn0; m1 = mn1;

        float ls0 = 0.f, ls1 = 0.f;
        #pragma unroll
        for (int nt = 0; nt < 8; nt++) {
            float p0 = __expf(c[nt][0] - mn0);
            float p1 = __expf(c[nt][1] - mn0);
            float p2 = __expf(c[nt][2] - mn1);
            float p3 = __expf(c[nt][3] - mn1);
            ls0 += p0 + p1; ls1 += p2 + p3;
            *(float2*)&Ps[qw + gid    ][nt * 8 + tig * 2] =
                make_float2(to_tf32(p0), to_tf32(p1));
            *(float2*)&Ps[qw + gid + 8][nt * 8 + tig * 2] =
                make_float2(to_tf32(p2), to_tf32(p3));
            O[nt][0] *= corr0; O[nt][1] *= corr0;
            O[nt][2] *= corr1; O[nt][3] *= corr1;
        }
        ls0 += __shfl_xor_sync(0xffffffffu, ls0, 1);
        ls0 += __shfl_xor_sync(0xffffffffu, ls0, 2);
        ls1 += __shfl_xor_sync(0xffffffffu, ls1, 1);
        ls1 += __shfl_xor_sync(0xffffffffu, ls1, 2);
        l0 = l0 * corr0 + ls0;
        l1 = l1 * corr1 + ls1;
        __syncwarp();   // Ps rows are warp-private

        // O[16 q][64 d] += P V on tensor pipe. A from Ps, B from Vs[d][t].
        #pragma unroll
        for (int ks = 0; ks < 8; ks++) {
            float a0 = Ps[qw + gid    ][ks * 8 + tig];
            float a1 = Ps[qw + gid + 8][ks * 8 + tig];
            float a2 = Ps[qw + gid    ][ks * 8 + tig + 4];
            float a3 = Ps[qw + gid + 8][ks * 8 + tig + 4];
            #pragma unroll
            for (int nt = 0; nt < 8; nt++) {
                float b0 = Vs[nt * 8 + gid][ks * 8 + tig];
                float b1 = Vs[nt * 8 + gid][ks * 8 + tig + 4];
                mma_tf32(O[nt][0], O[nt][1], O[nt][2], O[nt][3],
                         a0, a1, a2, a3, b0, b1);
            }
        }
    }

    // Normalize and write to [B,S,C], c = head*64 + d.
    const float inv0 = 1.f / l0, inv1 = 1.f / l1;
    const size_t row0 = (size_t)b * SEQ + s0 + qw + gid;
    const size_t row1 = row0 + 8;
    #pragma unroll
    for (int nt = 0; nt < 8; nt++) {
        const int col = n * HDIM + nt * 8 + tig * 2;
        *(float2*)&out[row0 * CH + col] =
            make_float2(O[nt][0] * inv0, O[nt][1] * inv0);
        *(float2*)&out[row1 * CH + col] =
            make_float2(O[nt][2] * inv1, O[nt][3] * inv1);
    }
}

// ---------------------------------------------------------------------------
// Launch
// ---------------------------------------------------------------------------
extern "C" void kernel_launch(void* const* d_in, const int* in_sizes, int n_in,
                              void* d_out, int out_size)
{
    const float* x        = (const float*)d_in[0];
    const float* gn_scale = (const float*)d_in[1];
    const float* gn_bias  = (const float*)d_in[2];
    const float* qkv_w    = (const float*)d_in[3];
    const float* qkv_b    = (const float*)d_in[4];
    const float* proj_w   = (const float*)d_in[5];
    const float* proj_b   = (const float*)d_in[6];
    const float* inl_w    = (const float*)d_in[7];
    const float* inl_b    = (const float*)d_in[8];
    float* out = (float*)d_out;

    float *hn, *qkv, *hfA, *hfB;
    cudaGetSymbolAddress((void**)&hn,  g_hn);
    cudaGetSymbolAddress((void**)&qkv, g_qkv);
    cudaGetSymbolAddress((void**)&hfA, g_hfA);
    cudaGetSymbolAddress((void**)&hfB, g_hfB);

    // 1) GroupNorm -> g_hn [B,S,C]
    gn_kernel<<<BATCH * NGRP, 256>>>(x, gn_scale, gn_bias, hn);

    // 2) qkv = W_qkv @ hn^T per batch -> g_qkv [B,3C,S]
    gemm_nt<0><<<dim3(SEQ / 128, (3 * CH) / 128, BATCH), 256>>>(
        qkv_w, hn, qkv_b, nullptr, qkv,
        3 * CH, SEQ, CH,
        (size_t)SEQ * CH, (size_t)3 * CH * SEQ, 0);

    // 3) Flash attention (tf32 mma) -> g_hfA [B,S,C]
    cudaFuncSetAttribute(flash_kernel,
                         cudaFuncAttributeMaxDynamicSharedMemorySize, FLASH_SMEM);
    flash_kernel<<<dim3(SEQ / 64, BATCH * NHEAD), 128, FLASH_SMEM>>>(qkv, hfA);

    // 4) INL: 3x Euler steps, ping-pong A->B->A->B
    const dim3 inl_grid(CH / 128, (BATCH * SEQ) / 128, 1);
    gemm_nt<1><<<inl_grid, 256>>>(hfA, inl_w, inl_b, hfA, hfB,
                                  BATCH * SEQ, CH, CH, 0, 0, 0);
    gemm_nt<1><<<inl_grid, 256>>>(hfB, inl_w, inl_b, hfB, hfA,
                                  BATCH * SEQ, CH, CH, 0, 0, 0);
    gemm_nt<1><<<inl_grid, 256>>>(hfA, inl_w, inl_b, hfA, hfB,
                                  BATCH * SEQ, CH, CH, 0, 0, 0);

    // 5) proj + residual -> out [B,C,H,W]
    gemm_nt<2><<<dim3(SEQ / 128, CH / 128, BATCH), 256>>>(
        proj_w, hfB, proj_b, x, out,
        CH, SEQ, CH,
        (size_t)SEQ * CH, (size_t)CH * SEQ, (size_t)CH * SEQ);
}